// round 5
// baseline (speedup 1.0000x reference)
#include <cuda_runtime.h>
#include <math.h>

// Problem dims
#define BB   8
#define TT   2048
#define DD   300
#define KK   10
#define LL   8921
#define TP   2057     // TT + KK - 1
#define LP   8960     // L padded to 70*128
#define ETP  2208     // padded embed row: 9 halo + 2048 + headroom for t0+k+r
#define HTP2 2176     // padded conv-out row (17*128)
#define OP2  384      // o padded to 3*128

// Scratch (device globals, zero-initialized; padding regions never written)
__device__ float g_Et[BB * DD * ETP];     // padded embeddings: [b][d][9 + tau]
__device__ float g_Hs[BB * DD * HTP2];    // conv output h: [b][d][t']
__device__ float g_Wt[KK * DD * OP2];     // conv_w transposed: [k][i][o]
__device__ float g_Ut[DD * LP];           // U transposed: [d][l]

// ---------------------------------------------------------------------------
// Kernel 1: embedding gather + transpose -> Et[b][d][9 + tau]
// ---------------------------------------------------------------------------
__global__ void k_gather(const int* __restrict__ ids, const float* __restrict__ emb) {
    __shared__ float sm[32][301];
    int b = blockIdx.y;
    int tau0 = blockIdx.x * 32;
    int tid = threadIdx.x;
    for (int idx = tid; idx < 32 * DD; idx += 256) {
        int r = idx / DD, c = idx - r * DD;
        int row = ids[b * TT + tau0 + r];
        sm[r][c] = emb[row * DD + c];
    }
    __syncthreads();
    for (int idx = tid; idx < DD * 32; idx += 256) {
        int i = idx >> 5, j = idx & 31;
        g_Et[(b * DD + i) * ETP + 9 + tau0 + j] = sm[j][i];
    }
}

// ---------------------------------------------------------------------------
// Kernel 2: conv_w (O,I,K) -> Wt[k][i][o]  (o padded to OP2, pad stays 0)
// ---------------------------------------------------------------------------
__global__ void k_wt(const float* __restrict__ w) {
    int idx = blockIdx.x * 256 + threadIdx.x;
    if (idx >= DD * DD * KK) return;
    int o = idx % DD;
    int rem = idx / DD;
    int i = rem % DD;
    int k = rem / DD;
    g_Wt[(k * DD + i) * OP2 + o] = w[(o * DD + i) * KK + k];
}

// ---------------------------------------------------------------------------
// Kernel 3: U (L,D) -> Ut[d][l]  (zero-padded to LP)
// ---------------------------------------------------------------------------
__global__ void k_ut(const float* __restrict__ U) {
    __shared__ float sm[32][33];
    int lt = blockIdx.x * 32, dt = blockIdx.y * 32;
    int tx = threadIdx.x, ty = threadIdx.y;
    int l = lt + ty, d = dt + tx;
    sm[ty][tx] = (l < LL && d < DD) ? U[l * DD + d] : 0.f;
    __syncthreads();
    int dd = dt + ty, ll = lt + tx;
    if (dd < DD) g_Ut[dd * LP + ll] = sm[tx][ty];
}

// ---------------------------------------------------------------------------
// Shared 128x128 GEMM inner step: 8x8 microtile, 4 FMA per smem float
// ---------------------------------------------------------------------------
#define GEMM_MICRO(As, Bs, acc, tx, ty)                                       \
    _Pragma("unroll")                                                         \
    for (int kk = 0; kk < 20; kk++) {                                         \
        float4 a0 = *(const float4*)&As[kk][ty * 4];                          \
        float4 a1 = *(const float4*)&As[kk][64 + ty * 4];                     \
        float4 b0 = *(const float4*)&Bs[kk][tx * 4];                          \
        float4 b1 = *(const float4*)&Bs[kk][64 + tx * 4];                     \
        float av[8] = {a0.x, a0.y, a0.z, a0.w, a1.x, a1.y, a1.z, a1.w};       \
        float bv[8] = {b0.x, b0.y, b0.z, b0.w, b1.x, b1.y, b1.z, b1.w};       \
        _Pragma("unroll")                                                     \
        for (int m = 0; m < 8; m++)                                           \
            _Pragma("unroll")                                                 \
            for (int n = 0; n < 8; n++) acc[m][n] += av[m] * bv[n];           \
    }

// ---------------------------------------------------------------------------
// Kernel 4: conv1d as GEMM over (k,i) -> Hs = relu(conv + bias)
//   block: 128 o x 128 t', 256 threads, 8x8 microtile, BK=20, no inner branches
// ---------------------------------------------------------------------------
__global__ void __launch_bounds__(256, 2) k_conv(const float* __restrict__ conv_b) {
    __shared__ float As[20][128];
    __shared__ float Bs[20][128];
    int t0 = blockIdx.x * 128;
    int o0 = blockIdx.y * 128;
    int b  = blockIdx.z;
    int tid = threadIdx.x;
    int tx = tid & 15, ty = tid >> 4;

    float acc[8][8] = {};
    const float* eb = g_Et + b * DD * ETP;

    for (int k = 0; k < KK; k++) {
        const float* wk = g_Wt + k * DD * OP2 + o0;
        const float* ek = eb + t0 + k;          // Etp[i][t0+k+r] == E[t0+r+k-9]
        for (int ic = 0; ic < 15; ic++) {
#pragma unroll
            for (int j = 0; j < 10; j++) {
                int idx = tid + j * 256;
                int c = idx >> 7, r = idx & 127;
                As[c][r] = wk[(ic * 20 + c) * OP2 + r];
                Bs[c][r] = ek[(ic * 20 + c) * ETP + r];
            }
            __syncthreads();
            GEMM_MICRO(As, Bs, acc, tx, ty)
            __syncthreads();
        }
    }

#pragma unroll
    for (int m = 0; m < 8; m++) {
        int o = o0 + (m >> 2) * 64 + ty * 4 + (m & 3);
        if (o >= DD) continue;
        float bias = conv_b[o];
        float* hrow = g_Hs + (b * DD + o) * HTP2;
#pragma unroll
        for (int n = 0; n < 8; n++) {
            int t = t0 + (n >> 2) * 64 + tx * 4 + (n & 3);
            if (t < TP) hrow[t] = fmaxf(acc[m][n] + bias, 0.f);
        }
    }
}

// ---------------------------------------------------------------------------
// Kernel 5: fused score-GEMM + online softmax
//   logits[b,l] = sum_t softmax_t(s)*s + fc_bias, s = U.h
//   block: (b, 128 l-rows), 17 t-tiles of 128; state in smem
// ---------------------------------------------------------------------------
__global__ void __launch_bounds__(256, 2) k_attn(const float* __restrict__ fc_bias,
                                                 float* __restrict__ out) {
    __shared__ float As[20][128];
    __shared__ float Bs[20][128];
    __shared__ float s_m[128], s_e[128], s_s[128];
    int l0 = blockIdx.x * 128;
    int b  = blockIdx.y;
    int tid = threadIdx.x;
    int tx = tid & 15, ty = tid >> 4;

    if (tid < 128) { s_m[tid] = -INFINITY; s_e[tid] = 0.f; s_s[tid] = 0.f; }
    const float* hb = g_Hs + b * DD * HTP2;
    const float* ub = g_Ut + l0;
    __syncthreads();

    for (int t0 = 0; t0 < TP; t0 += 128) {
        float acc[8][8] = {};
        for (int ic = 0; ic < 15; ic++) {
#pragma unroll
            for (int j = 0; j < 10; j++) {
                int idx = tid + j * 256;
                int c = idx >> 7, r = idx & 127;
                As[c][r] = ub[(ic * 20 + c) * LP + r];           // pad rows are 0
                Bs[c][r] = hb[(ic * 20 + c) * HTP2 + t0 + r];    // tail is 0
            }
            __syncthreads();
            GEMM_MICRO(As, Bs, acc, tx, ty)
            __syncthreads();
        }

        // online softmax update, one l-row spread over the 16 tx lanes
#pragma unroll
        for (int m = 0; m < 8; m++) {
            int row = (m >> 2) * 64 + ty * 4 + (m & 3);
            float mx = -INFINITY;
#pragma unroll
            for (int n = 0; n < 8; n++) {
                int t = t0 + (n >> 2) * 64 + tx * 4 + (n & 3);
                if (t < TP) mx = fmaxf(mx, acc[m][n]);
            }
#pragma unroll
            for (int off = 8; off; off >>= 1)
                mx = fmaxf(mx, __shfl_xor_sync(0xffffffffu, mx, off));

            float pe = 0.f, ps = 0.f;
#pragma unroll
            for (int n = 0; n < 8; n++) {
                int t = t0 + (n >> 2) * 64 + tx * 4 + (n & 3);
                if (t < TP) {
                    float p = __expf(acc[m][n] - mx);
                    pe += p;
                    ps += p * acc[m][n];
                }
            }
#pragma unroll
            for (int off = 8; off; off >>= 1) {
                pe += __shfl_xor_sync(0xffffffffu, pe, off);
                ps += __shfl_xor_sync(0xffffffffu, ps, off);
            }

            float mo = s_m[row];
            float mn = fmaxf(mo, mx);
            float ea = __expf(mo - mn);
            float eb2 = __expf(mx - mn);
            if (tx == 0) {
                s_e[row] = s_e[row] * ea + pe * eb2;
                s_s[row] = s_s[row] * ea + ps * eb2;
                s_m[row] = mn;
            }
        }
        __syncthreads();
    }

    if (tid < 128) {
        int l = l0 + tid;
        if (l < LL) out[b * LL + l] = s_s[tid] / s_e[tid] + fc_bias[l];
    }
}

// ---------------------------------------------------------------------------
// Launch
// ---------------------------------------------------------------------------
extern "C" void kernel_launch(void* const* d_in, const int* in_sizes, int n_in,
                              void* d_out, int out_size) {
    const int* ids = nullptr;
    const float *emb = nullptr, *cw = nullptr, *cb = nullptr, *U = nullptr, *fb = nullptr;
    for (int i = 0; i < n_in; i++) {
        switch (in_sizes[i]) {
            case BB * TT:          ids = (const int*)d_in[i];  break;
            case 50000 * DD:       emb = (const float*)d_in[i]; break;
            case DD * DD * KK:     cw  = (const float*)d_in[i]; break;
            case DD:               cb  = (const float*)d_in[i]; break;
            case LL * DD:          U   = (const float*)d_in[i]; break;
            case LL:               fb  = (const float*)d_in[i]; break;
            default: break;
        }
    }
    float* out = (float*)d_out;

    k_wt<<<(DD * DD * KK + 255) / 256, 256>>>(cw);
    k_ut<<<dim3(LP / 32, (DD + 31) / 32), dim3(32, 32)>>>(U);
    k_gather<<<dim3(TT / 32, BB), 256>>>(ids, emb);
    k_conv<<<dim3((TP + 127) / 128, (OP2) / 128, BB), 256>>>(cb);
    k_attn<<<dim3(LP / 128, BB), 256>>>(fb, out);
}

// round 8
// speedup vs baseline: 1.6838x; 1.6838x over previous
#include <cuda_runtime.h>
#include <cuda_bf16.h>
#include <cstdint>
#include <math.h>

typedef unsigned int u32;

// Problem dims
#define BB   8
#define TT   2048
#define DD   300
#define KK   10
#define LL   8921
#define TP   2057     // TT + KK - 1
#define LP   8960     // L padded to 70*128
#define ETP  2208     // padded embed row: 9 halo + 2048 + headroom
#define OP2  384      // o padded to 3*128
#define DP   320      // d padded to 20*16
#define TPAD 2176     // t' padded to 17*128
#define SSTR 40       // smem row stride in bf16 (80B)

// Scratch (device globals, zero-initialized; padding regions never written)
__device__ float g_Et[BB * DD * ETP];
__device__ float g_Wt[KK * DD * OP2];
__device__ __align__(16) __nv_bfloat16 g_Uhi[LP * DP];
__device__ __align__(16) __nv_bfloat16 g_Ulo[LP * DP];
__device__ __align__(16) __nv_bfloat16 g_Hthi[BB * TPAD * DP];
__device__ __align__(16) __nv_bfloat16 g_Htlo[BB * TPAD * DP];

// ---------------------------------------------------------------------------
// PTX helpers
// ---------------------------------------------------------------------------
__device__ __forceinline__ u32 smem_u32(const void* p) {
    return (u32)__cvta_generic_to_shared(p);
}

__device__ __forceinline__ void ldsm4(u32* r, u32 addr) {
    asm volatile("ldmatrix.sync.aligned.m8n8.x4.shared.b16 {%0,%1,%2,%3}, [%4];"
                 : "=r"(r[0]), "=r"(r[1]), "=r"(r[2]), "=r"(r[3])
                 : "r"(addr));
}

__device__ __forceinline__ void mma16816(float* d, const u32* a, const u32* b) {
    asm volatile(
        "mma.sync.aligned.m16n8k16.row.col.f32.bf16.bf16.f32 "
        "{%0,%1,%2,%3}, {%4,%5,%6,%7}, {%8,%9}, {%0,%1,%2,%3};"
        : "+f"(d[0]), "+f"(d[1]), "+f"(d[2]), "+f"(d[3])
        : "r"(a[0]), "r"(a[1]), "r"(a[2]), "r"(a[3]), "r"(b[0]), "r"(b[1]));
}

// ---------------------------------------------------------------------------
// Kernel 1: embedding gather + transpose -> Et[b][d][9+tau]
// ---------------------------------------------------------------------------
__global__ void k_gather(const int* __restrict__ ids, const float* __restrict__ emb) {
    __shared__ float sm[32][301];
    int b = blockIdx.y;
    int tau0 = blockIdx.x * 32;
    int tid = threadIdx.x;
    for (int idx = tid; idx < 32 * DD; idx += 256) {
        int r = idx / DD;
        int c = idx - r * DD;
        int row = ids[b * TT + tau0 + r];
        sm[r][c] = emb[row * DD + c];
    }
    __syncthreads();
    for (int idx = tid; idx < DD * 32; idx += 256) {
        int i = idx >> 5;
        int j = idx & 31;
        g_Et[(b * DD + i) * ETP + 9 + tau0 + j] = sm[j][i];
    }
}

// ---------------------------------------------------------------------------
// Kernel 2: conv_w (O,I,K) -> Wt[k][i][o]
// ---------------------------------------------------------------------------
__global__ void k_wt(const float* __restrict__ w) {
    int idx = blockIdx.x * 256 + threadIdx.x;
    if (idx >= DD * DD * KK) { return; }
    int o = idx % DD;
    int rem = idx / DD;
    int i = rem % DD;
    int k = rem / DD;
    g_Wt[(k * DD + i) * OP2 + o] = w[(o * DD + i) * KK + k];
}

// ---------------------------------------------------------------------------
// Kernel 3: U fp32 [l][d] -> bf16 hi/lo split [l][DP]
// ---------------------------------------------------------------------------
__global__ void k_usplit(const float* __restrict__ U) {
    int idx = blockIdx.x * 256 + threadIdx.x;
    if (idx >= LL * DD) { return; }
    int l = idx / DD;
    int d = idx - l * DD;
    float u = U[idx];
    __nv_bfloat16 h = __float2bfloat16(u);
    g_Uhi[l * DP + d] = h;
    g_Ulo[l * DP + d] = __float2bfloat16(u - __bfloat162float(h));
}

// ---------------------------------------------------------------------------
// Kernel 4: conv1d as fp32 GEMM; epilogue: relu(+bias), bf16 hi/lo split,
//           write TRANSPOSED -> Ht[b][t][d]
// ---------------------------------------------------------------------------
__global__ void __launch_bounds__(256, 2) k_conv(const float* __restrict__ conv_b) {
    __shared__ float As[20][128];
    __shared__ float Bs[20][128];
    int t0 = blockIdx.x * 128;
    int o0 = blockIdx.y * 128;
    int b  = blockIdx.z;
    int tid = threadIdx.x;
    int tx = tid & 15;
    int ty = tid >> 4;

    float acc[8][8];
#pragma unroll
    for (int m = 0; m < 8; m++) {
#pragma unroll
        for (int n = 0; n < 8; n++) { acc[m][n] = 0.f; }
    }

    const float* eb = g_Et + b * DD * ETP;

    for (int k = 0; k < KK; k++) {
        const float* wk = g_Wt + k * DD * OP2 + o0;
        const float* ek = eb + t0 + k;
        for (int ic = 0; ic < 15; ic++) {
#pragma unroll
            for (int j = 0; j < 10; j++) {
                int idx = tid + j * 256;
                int c = idx >> 7;
                int r = idx & 127;
                As[c][r] = wk[(ic * 20 + c) * OP2 + r];
                Bs[c][r] = ek[(ic * 20 + c) * ETP + r];
            }
            __syncthreads();
#pragma unroll
            for (int kk = 0; kk < 20; kk++) {
                float4 a0 = *(const float4*)&As[kk][ty * 4];
                float4 a1 = *(const float4*)&As[kk][64 + ty * 4];
                float4 b0 = *(const float4*)&Bs[kk][tx * 4];
                float4 b1 = *(const float4*)&Bs[kk][64 + tx * 4];
                float av[8] = {a0.x, a0.y, a0.z, a0.w, a1.x, a1.y, a1.z, a1.w};
                float bv[8] = {b0.x, b0.y, b0.z, b0.w, b1.x, b1.y, b1.z, b1.w};
#pragma unroll
                for (int m = 0; m < 8; m++) {
#pragma unroll
                    for (int n = 0; n < 8; n++) { acc[m][n] += av[m] * bv[n]; }
                }
            }
            __syncthreads();
        }
    }

    float biasv[8];
#pragma unroll
    for (int m = 0; m < 8; m++) {
        int o = o0 + (m >> 2) * 64 + ty * 4 + (m & 3);
        biasv[m] = (o < DD) ? conv_b[o] : 0.f;
    }

#pragma unroll
    for (int n = 0; n < 8; n++) {
        int t = t0 + (n >> 2) * 64 + tx * 4 + (n & 3);
        if (t < TP) {
            size_t rowbase = ((size_t)b * TPAD + t) * DP;
#pragma unroll
            for (int grp = 0; grp < 2; grp++) {
                int ob = o0 + grp * 64 + ty * 4;
                if (ob < DD) {
                    __nv_bfloat16 hv[4];
                    __nv_bfloat16 lv[4];
#pragma unroll
                    for (int mm = 0; mm < 4; mm++) {
                        float v = fmaxf(acc[grp * 4 + mm][n] + biasv[grp * 4 + mm], 0.f);
                        hv[mm] = __float2bfloat16(v);
                        lv[mm] = __float2bfloat16(v - __bfloat162float(hv[mm]));
                    }
                    *(uint2*)&g_Hthi[rowbase + ob] = *(uint2*)hv;
                    *(uint2*)&g_Htlo[rowbase + ob] = *(uint2*)lv;
                }
            }
        }
    }
}

// ---------------------------------------------------------------------------
// Kernel 5: fused score-GEMM (bf16-split mma.sync) + online softmax
//   block: 128 l x 128 t-tile, 8 warps (4 m-stripes x 2 n-halves)
// ---------------------------------------------------------------------------
__global__ void __launch_bounds__(256, 2) k_attn(const float* __restrict__ fc_bias,
                                                 float* __restrict__ out) {
    __shared__ __align__(16) __nv_bfloat16 sAh[128 * SSTR];
    __shared__ __align__(16) __nv_bfloat16 sAl[128 * SSTR];
    __shared__ __align__(16) __nv_bfloat16 sBh[128 * SSTR];
    __shared__ __align__(16) __nv_bfloat16 sBl[128 * SSTR];
    __shared__ float s_m[128];
    __shared__ float s_e[128];
    __shared__ float s_s[128];
    __shared__ float p_m[2][128];
    __shared__ float p_e[2][128];
    __shared__ float p_s[2][128];

    int l0 = blockIdx.x * 128;
    int b  = blockIdx.y;
    int tid = threadIdx.x;
    int lane = tid & 31;
    int warp = tid >> 5;
    int warp_m = warp >> 1;
    int warp_n = warp & 1;
    int g = lane >> 2;
    int q = lane & 3;

    if (tid < 128) {
        s_m[tid] = -INFINITY;
        s_e[tid] = 0.f;
        s_s[tid] = 0.f;
    }

    u32 uAh = smem_u32(sAh);
    u32 uAl = smem_u32(sAl);
    u32 uBh = smem_u32(sBh);
    u32 uBl = smem_u32(sBl);

    // ldmatrix fragment base addresses (bytes)
    u32 aoff0 = (u32)(((warp_m * 32 + 0  + (lane & 15)) * SSTR + (lane >> 4) * 8) * 2);
    u32 aoff1 = (u32)(((warp_m * 32 + 16 + (lane & 15)) * SSTR + (lane >> 4) * 8) * 2);
    u32 boff[4];
    {
        int bidx = lane >> 3;
        int brow_add = (bidx >> 1) * 8 + (lane & 7);
        int bcol = (bidx & 1) * 8;
#pragma unroll
        for (int j2 = 0; j2 < 4; j2++) {
            boff[j2] = (u32)(((warp_n * 64 + j2 * 16 + brow_add) * SSTR + bcol) * 2);
        }
    }

    const __nv_bfloat16* Bhi = g_Hthi + (size_t)b * TPAD * DP;
    const __nv_bfloat16* Blo = g_Htlo + (size_t)b * TPAD * DP;

    for (int t0 = 0; t0 < TPAD; t0 += 128) {
        float acc[2][8][4];
#pragma unroll
        for (int mt = 0; mt < 2; mt++) {
#pragma unroll
            for (int j = 0; j < 8; j++) {
#pragma unroll
                for (int c = 0; c < 4; c++) { acc[mt][j][c] = 0.f; }
            }
        }

        for (int ph = 0; ph < 10; ph++) {
            int d0 = ph * 32;
            __syncthreads();
#pragma unroll
            for (int it = 0; it < 2; it++) {
                int idx = tid + it * 256;
                int row = idx >> 2;
                int qd = (idx & 3) * 8;
                int so = row * SSTR + qd;
                *(uint4*)&sAh[so] = *(const uint4*)&g_Uhi[(size_t)(l0 + row) * DP + d0 + qd];
                *(uint4*)&sAl[so] = *(const uint4*)&g_Ulo[(size_t)(l0 + row) * DP + d0 + qd];
                *(uint4*)&sBh[so] = *(const uint4*)&Bhi[(size_t)(t0 + row) * DP + d0 + qd];
                *(uint4*)&sBl[so] = *(const uint4*)&Blo[(size_t)(t0 + row) * DP + d0 + qd];
            }
            __syncthreads();

#pragma unroll
            for (int kc = 0; kc < 2; kc++) {
                u32 kb = (u32)(kc * 32);  // 16 bf16 = 32 bytes
                u32 ah0[4];
                u32 ah1[4];
                u32 al0[4];
                u32 al1[4];
                u32 bhf[4][4];
                u32 blf[4][4];

                ldsm4(ah0, uAh + aoff0 + kb);
                ldsm4(ah1, uAh + aoff1 + kb);
#pragma unroll
                for (int j2 = 0; j2 < 4; j2++) { ldsm4(bhf[j2], uBh + boff[j2] + kb); }

                // pass 1: hi*hi
#pragma unroll
                for (int j = 0; j < 8; j++) {
                    const u32* bp = &bhf[j >> 1][(j & 1) * 2];
                    mma16816(acc[0][j], ah0, bp);
                    mma16816(acc[1][j], ah1, bp);
                }

                // pass 2: lo*hi
                ldsm4(al0, uAl + aoff0 + kb);
                ldsm4(al1, uAl + aoff1 + kb);
#pragma unroll
                for (int j = 0; j < 8; j++) {
                    const u32* bp = &bhf[j >> 1][(j & 1) * 2];
                    mma16816(acc[0][j], al0, bp);
                    mma16816(acc[1][j], al1, bp);
                }

                // pass 3: hi*lo
#pragma unroll
                for (int j2 = 0; j2 < 4; j2++) { ldsm4(blf[j2], uBl + boff[j2] + kb); }
#pragma unroll
                for (int j = 0; j < 8; j++) {
                    const u32* bp = &blf[j >> 1][(j & 1) * 2];
                    mma16816(acc[0][j], ah0, bp);
                    mma16816(acc[1][j], ah1, bp);
                }
            }
        }

        // per-warp partial softmax stats for this t-tile
#pragma unroll
        for (int mt = 0; mt < 2; mt++) {
#pragma unroll
            for (int ch = 0; ch < 2; ch++) {
                int row = warp_m * 32 + mt * 16 + g + ch * 8;
                float mx = -INFINITY;
#pragma unroll
                for (int j = 0; j < 8; j++) {
#pragma unroll
                    for (int bb2 = 0; bb2 < 2; bb2++) {
                        int t = t0 + warp_n * 64 + j * 8 + q * 2 + bb2;
                        if (t < TP) { mx = fmaxf(mx, acc[mt][j][ch * 2 + bb2]); }
                    }
                }
                mx = fmaxf(mx, __shfl_xor_sync(0xffffffffu, mx, 1));
                mx = fmaxf(mx, __shfl_xor_sync(0xffffffffu, mx, 2));

                float pe = 0.f;
                float ps = 0.f;
#pragma unroll
                for (int j = 0; j < 8; j++) {
#pragma unroll
                    for (int bb2 = 0; bb2 < 2; bb2++) {
                        int t = t0 + warp_n * 64 + j * 8 + q * 2 + bb2;
                        if (t < TP) {
                            float v = acc[mt][j][ch * 2 + bb2];
                            float p = __expf(v - mx);
                            pe += p;
                            ps += p * v;
                        }
                    }
                }
                pe += __shfl_xor_sync(0xffffffffu, pe, 1);
                ps += __shfl_xor_sync(0xffffffffu, ps, 1);
                pe += __shfl_xor_sync(0xffffffffu, pe, 2);
                ps += __shfl_xor_sync(0xffffffffu, ps, 2);

                if (q == 0) {
                    p_m[warp_n][row] = mx;
                    p_e[warp_n][row] = pe;
                    p_s[warp_n][row] = ps;
                }
            }
        }
        __syncthreads();

        if (tid < 128) {
            float mo = s_m[tid];
            float eo = s_e[tid];
            float so = s_s[tid];
#pragma unroll
            for (int p = 0; p < 2; p++) {
                float mx = p_m[p][tid];
                float pe = p_e[p][tid];
                float ps = p_s[p][tid];
                float mn = fmaxf(mo, mx);
                float e1 = __expf(mo - mn);
                float e2 = __expf(mx - mn);
                eo = eo * e1 + pe * e2;
                so = so * e1 + ps * e2;
                mo = mn;
            }
            s_m[tid] = mo;
            s_e[tid] = eo;
            s_s[tid] = so;
        }
        __syncthreads();
    }

    if (tid < 128) {
        int l = l0 + tid;
        if (l < LL) { out[b * LL + l] = s_s[tid] / s_e[tid] + fc_bias[l]; }
    }
}

// ---------------------------------------------------------------------------
// Launch
// ---------------------------------------------------------------------------
extern "C" void kernel_launch(void* const* d_in, const int* in_sizes, int n_in,
                              void* d_out, int out_size) {
    const int* ids = nullptr;
    const float* emb = nullptr;
    const float* cw = nullptr;
    const float* cb = nullptr;
    const float* U = nullptr;
    const float* fb = nullptr;
    for (int i = 0; i < n_in; i++) {
        int s = in_sizes[i];
        if (s == BB * TT) { ids = (const int*)d_in[i]; }
        else if (s == 50000 * DD) { emb = (const float*)d_in[i]; }
        else if (s == DD * DD * KK) { cw = (const float*)d_in[i]; }
        else if (s == DD) { cb = (const float*)d_in[i]; }
        else if (s == LL * DD) { U = (const float*)d_in[i]; }
        else if (s == LL) { fb = (const float*)d_in[i]; }
    }
    float* out = (float*)d_out;

    k_wt<<<(DD * DD * KK + 255) / 256, 256>>>(cw);
    k_usplit<<<(LL * DD + 255) / 256, 256>>>(U);
    k_gather<<<dim3(TT / 32, BB), 256>>>(ids, emb);
    k_conv<<<dim3(TPAD / 128, OP2 / 128, BB), 256>>>(cb);
    k_attn<<<dim3(LP / 128, BB), 256>>>(fb, out);
}

// round 9
// speedup vs baseline: 2.2531x; 1.3382x over previous
#include <cuda_runtime.h>
#include <cuda_bf16.h>
#include <cstdint>
#include <math.h>

typedef unsigned int u32;

// Problem dims
#define BB   8
#define TT   2048
#define DD   300
#define KK   10
#define LL   8921
#define TP   2057     // TT + KK - 1
#define LP   8960     // L padded to 70*128
#define OP2  384      // o padded to 3*128
#define DP   320      // d padded to 20*16
#define TPAD 2176     // t' padded to 17*128
#define ETR  2208     // embed rows: 9 halo + 2048 + tail zeros (need up to 2184)
#define SSTR 40       // smem row stride in bf16 (80B)

// Scratch (device globals, zero-initialized; padding regions never written)
__device__ __align__(16) __nv_bfloat16 g_Ehi[BB * ETR * DP];   // [b][9+tau][d]
__device__ __align__(16) __nv_bfloat16 g_Elo[BB * ETR * DP];
__device__ __align__(16) __nv_bfloat16 g_Whi[KK * OP2 * DP];   // [k][o][i]
__device__ __align__(16) __nv_bfloat16 g_Wlo[KK * OP2 * DP];
__device__ __align__(16) __nv_bfloat16 g_Uhi[LP * DP];         // [l][d]
__device__ __align__(16) __nv_bfloat16 g_Ulo[LP * DP];
__device__ __align__(16) __nv_bfloat16 g_Hthi[BB * TPAD * DP]; // [b][t][d=o]
__device__ __align__(16) __nv_bfloat16 g_Htlo[BB * TPAD * DP];

// ---------------------------------------------------------------------------
// PTX helpers
// ---------------------------------------------------------------------------
__device__ __forceinline__ u32 smem_u32(const void* p) {
    return (u32)__cvta_generic_to_shared(p);
}

__device__ __forceinline__ void ldsm4(u32* r, u32 addr) {
    asm volatile("ldmatrix.sync.aligned.m8n8.x4.shared.b16 {%0,%1,%2,%3}, [%4];"
                 : "=r"(r[0]), "=r"(r[1]), "=r"(r[2]), "=r"(r[3])
                 : "r"(addr));
}

__device__ __forceinline__ void mma16816(float* d, const u32* a, const u32* b) {
    asm volatile(
        "mma.sync.aligned.m16n8k16.row.col.f32.bf16.bf16.f32 "
        "{%0,%1,%2,%3}, {%4,%5,%6,%7}, {%8,%9}, {%0,%1,%2,%3};"
        : "+f"(d[0]), "+f"(d[1]), "+f"(d[2]), "+f"(d[3])
        : "r"(a[0]), "r"(a[1]), "r"(a[2]), "r"(a[3]), "r"(b[0]), "r"(b[1]));
}

// ---------------------------------------------------------------------------
// Kernel 1: embedding gather + bf16 hi/lo split -> Ehi/Elo[b][9+tau][d]
// ---------------------------------------------------------------------------
__global__ void k_gather(const int* __restrict__ ids, const float* __restrict__ emb) {
    int idx = blockIdx.x * 256 + threadIdx.x;
    if (idx >= BB * TT * DD) { return; }
    int d = idx % DD;
    int tok = idx / DD;
    int b = tok / TT;
    int tau = tok - b * TT;
    int row = ids[tok];
    float v = emb[row * DD + d];
    __nv_bfloat16 h = __float2bfloat16(v);
    size_t o = ((size_t)b * ETR + 9 + tau) * DP + d;
    g_Ehi[o] = h;
    g_Elo[o] = __float2bfloat16(v - __bfloat162float(h));
}

// ---------------------------------------------------------------------------
// Kernel 2: conv_w (O,I,K) fp32 -> Whi/Wlo[k][o][i]
// ---------------------------------------------------------------------------
__global__ void k_wsplit(const float* __restrict__ w) {
    int idx = blockIdx.x * 256 + threadIdx.x;
    if (idx >= KK * DD * DD) { return; }
    int i = idx % DD;
    int rem = idx / DD;
    int o = rem % DD;
    int k = rem / DD;
    float v = w[(o * DD + i) * KK + k];
    __nv_bfloat16 h = __float2bfloat16(v);
    size_t dst = ((size_t)k * OP2 + o) * DP + i;
    g_Whi[dst] = h;
    g_Wlo[dst] = __float2bfloat16(v - __bfloat162float(h));
}

// ---------------------------------------------------------------------------
// Kernel 3: U fp32 [l][d] -> bf16 hi/lo split [l][DP]
// ---------------------------------------------------------------------------
__global__ void k_usplit(const float* __restrict__ U) {
    int idx = blockIdx.x * 256 + threadIdx.x;
    if (idx >= LL * DD) { return; }
    int l = idx / DD;
    int d = idx - l * DD;
    float u = U[idx];
    __nv_bfloat16 h = __float2bfloat16(u);
    g_Uhi[l * DP + d] = h;
    g_Ulo[l * DP + d] = __float2bfloat16(u - __bfloat162float(h));
}

// ---------------------------------------------------------------------------
// Kernel 4: conv1d via bf16-split mma. C[o,t] = sum_k sum_i W[k][o][i]*E[t+k][i]
//   block: 128 o x 128 t, 8 warps (4 m-stripes x 2 n-halves), 100 phases
//   epilogue: relu(+bias), hi/lo split, store transposed -> Ht[b][t][o]
// ---------------------------------------------------------------------------
__global__ void __launch_bounds__(256, 2) k_conv(const float* __restrict__ conv_b) {
    __shared__ __align__(16) __nv_bfloat16 sAh[128 * SSTR];
    __shared__ __align__(16) __nv_bfloat16 sAl[128 * SSTR];
    __shared__ __align__(16) __nv_bfloat16 sBh[128 * SSTR];
    __shared__ __align__(16) __nv_bfloat16 sBl[128 * SSTR];

    int t0 = blockIdx.x * 128;
    int o0 = blockIdx.y * 128;
    int b  = blockIdx.z;
    int tid = threadIdx.x;
    int lane = tid & 31;
    int warp = tid >> 5;
    int warp_m = warp >> 1;
    int warp_n = warp & 1;
    int g = lane >> 2;
    int q = lane & 3;

    u32 uAh = smem_u32(sAh);
    u32 uAl = smem_u32(sAl);
    u32 uBh = smem_u32(sBh);
    u32 uBl = smem_u32(sBl);

    u32 aoff0 = (u32)(((warp_m * 32 + 0  + (lane & 15)) * SSTR + (lane >> 4) * 8) * 2);
    u32 aoff1 = (u32)(((warp_m * 32 + 16 + (lane & 15)) * SSTR + (lane >> 4) * 8) * 2);
    u32 boff[4];
    {
        int bidx = lane >> 3;
        int brow_add = (bidx >> 1) * 8 + (lane & 7);
        int bcol = (bidx & 1) * 8;
#pragma unroll
        for (int j2 = 0; j2 < 4; j2++) {
            boff[j2] = (u32)(((warp_n * 64 + j2 * 16 + brow_add) * SSTR + bcol) * 2);
        }
    }

    float acc[2][8][4];
#pragma unroll
    for (int mt = 0; mt < 2; mt++) {
#pragma unroll
        for (int j = 0; j < 8; j++) {
#pragma unroll
            for (int c = 0; c < 4; c++) { acc[mt][j][c] = 0.f; }
        }
    }

    for (int k = 0; k < KK; k++) {
        const __nv_bfloat16* Ahi = g_Whi + (size_t)k * OP2 * DP + (size_t)o0 * DP;
        const __nv_bfloat16* Alo = g_Wlo + (size_t)k * OP2 * DP + (size_t)o0 * DP;
        const __nv_bfloat16* Bhi = g_Ehi + ((size_t)b * ETR + t0 + k) * DP;
        const __nv_bfloat16* Blo = g_Elo + ((size_t)b * ETR + t0 + k) * DP;

        for (int ph = 0; ph < 10; ph++) {
            int d0 = ph * 32;
            __syncthreads();
#pragma unroll
            for (int it = 0; it < 2; it++) {
                int idx = tid + it * 256;
                int row = idx >> 2;
                int qd = (idx & 3) * 8;
                int so = row * SSTR + qd;
                *(uint4*)&sAh[so] = *(const uint4*)&Ahi[(size_t)row * DP + d0 + qd];
                *(uint4*)&sAl[so] = *(const uint4*)&Alo[(size_t)row * DP + d0 + qd];
                *(uint4*)&sBh[so] = *(const uint4*)&Bhi[(size_t)row * DP + d0 + qd];
                *(uint4*)&sBl[so] = *(const uint4*)&Blo[(size_t)row * DP + d0 + qd];
            }
            __syncthreads();

#pragma unroll
            for (int kc = 0; kc < 2; kc++) {
                u32 kb = (u32)(kc * 32);
                u32 ah0[4];
                u32 ah1[4];
                u32 al0[4];
                u32 al1[4];
                u32 bhf[4][4];
                u32 blf[4][4];

                ldsm4(ah0, uAh + aoff0 + kb);
                ldsm4(ah1, uAh + aoff1 + kb);
#pragma unroll
                for (int j2 = 0; j2 < 4; j2++) { ldsm4(bhf[j2], uBh + boff[j2] + kb); }

#pragma unroll
                for (int j = 0; j < 8; j++) {
                    const u32* bp = &bhf[j >> 1][(j & 1) * 2];
                    mma16816(acc[0][j], ah0, bp);
                    mma16816(acc[1][j], ah1, bp);
                }

                ldsm4(al0, uAl + aoff0 + kb);
                ldsm4(al1, uAl + aoff1 + kb);
#pragma unroll
                for (int j = 0; j < 8; j++) {
                    const u32* bp = &bhf[j >> 1][(j & 1) * 2];
                    mma16816(acc[0][j], al0, bp);
                    mma16816(acc[1][j], al1, bp);
                }

#pragma unroll
                for (int j2 = 0; j2 < 4; j2++) { ldsm4(blf[j2], uBl + boff[j2] + kb); }
#pragma unroll
                for (int j = 0; j < 8; j++) {
                    const u32* bp = &blf[j >> 1][(j & 1) * 2];
                    mma16816(acc[0][j], ah0, bp);
                    mma16816(acc[1][j], ah1, bp);
                }
            }
        }
    }

    // Epilogue: bias + relu, hi/lo split, transposed element stores to [t][o]
    float biasv[2][2];
#pragma unroll
    for (int mt = 0; mt < 2; mt++) {
#pragma unroll
        for (int ch = 0; ch < 2; ch++) {
            int o = o0 + warp_m * 32 + mt * 16 + g + ch * 8;
            biasv[mt][ch] = (o < DD) ? conv_b[o] : 0.f;
        }
    }

#pragma unroll
    for (int mt = 0; mt < 2; mt++) {
#pragma unroll
        for (int ch = 0; ch < 2; ch++) {
            int o = o0 + warp_m * 32 + mt * 16 + g + ch * 8;
            if (o < DD) {
#pragma unroll
                for (int j = 0; j < 8; j++) {
#pragma unroll
                    for (int bb2 = 0; bb2 < 2; bb2++) {
                        int t = t0 + warp_n * 64 + j * 8 + q * 2 + bb2;
                        if (t < TP) {
                            float v = fmaxf(acc[mt][j][ch * 2 + bb2] + biasv[mt][ch], 0.f);
                            __nv_bfloat16 h = __float2bfloat16(v);
                            size_t dst = ((size_t)b * TPAD + t) * DP + o;
                            g_Hthi[dst] = h;
                            g_Htlo[dst] = __float2bfloat16(v - __bfloat162float(h));
                        }
                    }
                }
            }
        }
    }
}

// ---------------------------------------------------------------------------
// Kernel 5: fused score-GEMM (bf16-split mma.sync) + online softmax
//   block: 128 l x 128 t-tile, 8 warps (4 m-stripes x 2 n-halves)
// ---------------------------------------------------------------------------
__global__ void __launch_bounds__(256, 2) k_attn(const float* __restrict__ fc_bias,
                                                 float* __restrict__ out) {
    __shared__ __align__(16) __nv_bfloat16 sAh[128 * SSTR];
    __shared__ __align__(16) __nv_bfloat16 sAl[128 * SSTR];
    __shared__ __align__(16) __nv_bfloat16 sBh[128 * SSTR];
    __shared__ __align__(16) __nv_bfloat16 sBl[128 * SSTR];
    __shared__ float s_m[128];
    __shared__ float s_e[128];
    __shared__ float s_s[128];
    __shared__ float p_m[2][128];
    __shared__ float p_e[2][128];
    __shared__ float p_s[2][128];

    int l0 = blockIdx.x * 128;
    int b  = blockIdx.y;
    int tid = threadIdx.x;
    int lane = tid & 31;
    int warp = tid >> 5;
    int warp_m = warp >> 1;
    int warp_n = warp & 1;
    int g = lane >> 2;
    int q = lane & 3;

    if (tid < 128) {
        s_m[tid] = -INFINITY;
        s_e[tid] = 0.f;
        s_s[tid] = 0.f;
    }

    u32 uAh = smem_u32(sAh);
    u32 uAl = smem_u32(sAl);
    u32 uBh = smem_u32(sBh);
    u32 uBl = smem_u32(sBl);

    u32 aoff0 = (u32)(((warp_m * 32 + 0  + (lane & 15)) * SSTR + (lane >> 4) * 8) * 2);
    u32 aoff1 = (u32)(((warp_m * 32 + 16 + (lane & 15)) * SSTR + (lane >> 4) * 8) * 2);
    u32 boff[4];
    {
        int bidx = lane >> 3;
        int brow_add = (bidx >> 1) * 8 + (lane & 7);
        int bcol = (bidx & 1) * 8;
#pragma unroll
        for (int j2 = 0; j2 < 4; j2++) {
            boff[j2] = (u32)(((warp_n * 64 + j2 * 16 + brow_add) * SSTR + bcol) * 2);
        }
    }

    const __nv_bfloat16* Bhi = g_Hthi + (size_t)b * TPAD * DP;
    const __nv_bfloat16* Blo = g_Htlo + (size_t)b * TPAD * DP;

    for (int t0 = 0; t0 < TPAD; t0 += 128) {
        float acc[2][8][4];
#pragma unroll
        for (int mt = 0; mt < 2; mt++) {
#pragma unroll
            for (int j = 0; j < 8; j++) {
#pragma unroll
                for (int c = 0; c < 4; c++) { acc[mt][j][c] = 0.f; }
            }
        }

        for (int ph = 0; ph < 10; ph++) {
            int d0 = ph * 32;
            __syncthreads();
#pragma unroll
            for (int it = 0; it < 2; it++) {
                int idx = tid + it * 256;
                int row = idx >> 2;
                int qd = (idx & 3) * 8;
                int so = row * SSTR + qd;
                *(uint4*)&sAh[so] = *(const uint4*)&g_Uhi[(size_t)(l0 + row) * DP + d0 + qd];
                *(uint4*)&sAl[so] = *(const uint4*)&g_Ulo[(size_t)(l0 + row) * DP + d0 + qd];
                *(uint4*)&sBh[so] = *(const uint4*)&Bhi[(size_t)(t0 + row) * DP + d0 + qd];
                *(uint4*)&sBl[so] = *(const uint4*)&Blo[(size_t)(t0 + row) * DP + d0 + qd];
            }
            __syncthreads();

#pragma unroll
            for (int kc = 0; kc < 2; kc++) {
                u32 kb = (u32)(kc * 32);
                u32 ah0[4];
                u32 ah1[4];
                u32 al0[4];
                u32 al1[4];
                u32 bhf[4][4];
                u32 blf[4][4];

                ldsm4(ah0, uAh + aoff0 + kb);
                ldsm4(ah1, uAh + aoff1 + kb);
#pragma unroll
                for (int j2 = 0; j2 < 4; j2++) { ldsm4(bhf[j2], uBh + boff[j2] + kb); }

#pragma unroll
                for (int j = 0; j < 8; j++) {
                    const u32* bp = &bhf[j >> 1][(j & 1) * 2];
                    mma16816(acc[0][j], ah0, bp);
                    mma16816(acc[1][j], ah1, bp);
                }

                ldsm4(al0, uAl + aoff0 + kb);
                ldsm4(al1, uAl + aoff1 + kb);
#pragma unroll
                for (int j = 0; j < 8; j++) {
                    const u32* bp = &bhf[j >> 1][(j & 1) * 2];
                    mma16816(acc[0][j], al0, bp);
                    mma16816(acc[1][j], al1, bp);
                }

#pragma unroll
                for (int j2 = 0; j2 < 4; j2++) { ldsm4(blf[j2], uBl + boff[j2] + kb); }
#pragma unroll
                for (int j = 0; j < 8; j++) {
                    const u32* bp = &blf[j >> 1][(j & 1) * 2];
                    mma16816(acc[0][j], ah0, bp);
                    mma16816(acc[1][j], ah1, bp);
                }
            }
        }

        // per-warp partial softmax stats for this t-tile
#pragma unroll
        for (int mt = 0; mt < 2; mt++) {
#pragma unroll
            for (int ch = 0; ch < 2; ch++) {
                int row = warp_m * 32 + mt * 16 + g + ch * 8;
                float mx = -INFINITY;
#pragma unroll
                for (int j = 0; j < 8; j++) {
#pragma unroll
                    for (int bb2 = 0; bb2 < 2; bb2++) {
                        int t = t0 + warp_n * 64 + j * 8 + q * 2 + bb2;
                        if (t < TP) { mx = fmaxf(mx, acc[mt][j][ch * 2 + bb2]); }
                    }
                }
                mx = fmaxf(mx, __shfl_xor_sync(0xffffffffu, mx, 1));
                mx = fmaxf(mx, __shfl_xor_sync(0xffffffffu, mx, 2));

                float pe = 0.f;
                float ps = 0.f;
#pragma unroll
                for (int j = 0; j < 8; j++) {
#pragma unroll
                    for (int bb2 = 0; bb2 < 2; bb2++) {
                        int t = t0 + warp_n * 64 + j * 8 + q * 2 + bb2;
                        if (t < TP) {
                            float v = acc[mt][j][ch * 2 + bb2];
                            float p = __expf(v - mx);
                            pe += p;
                            ps += p * v;
                        }
                    }
                }
                pe += __shfl_xor_sync(0xffffffffu, pe, 1);
                ps += __shfl_xor_sync(0xffffffffu, ps, 1);
                pe += __shfl_xor_sync(0xffffffffu, pe, 2);
                ps += __shfl_xor_sync(0xffffffffu, ps, 2);

                if (q == 0) {
                    p_m[warp_n][row] = mx;
                    p_e[warp_n][row] = pe;
                    p_s[warp_n][row] = ps;
                }
            }
        }
        __syncthreads();

        if (tid < 128) {
            float mo = s_m[tid];
            float eo = s_e[tid];
            float so = s_s[tid];
#pragma unroll
            for (int p = 0; p < 2; p++) {
                float mx = p_m[p][tid];
                float pe = p_e[p][tid];
                float ps = p_s[p][tid];
                float mn = fmaxf(mo, mx);
                float e1 = __expf(mo - mn);
                float e2 = __expf(mx - mn);
                eo = eo * e1 + pe * e2;
                so = so * e1 + ps * e2;
                mo = mn;
            }
            s_m[tid] = mo;
            s_e[tid] = eo;
            s_s[tid] = so;
        }
        __syncthreads();
    }

    if (tid < 128) {
        int l = l0 + tid;
        if (l < LL) { out[b * LL + l] = s_s[tid] / s_e[tid] + fc_bias[l]; }
    }
}

// ---------------------------------------------------------------------------
// Launch
// ---------------------------------------------------------------------------
extern "C" void kernel_launch(void* const* d_in, const int* in_sizes, int n_in,
                              void* d_out, int out_size) {
    const int* ids = nullptr;
    const float* emb = nullptr;
    const float* cw = nullptr;
    const float* cb = nullptr;
    const float* U = nullptr;
    const float* fb = nullptr;
    for (int i = 0; i < n_in; i++) {
        int s = in_sizes[i];
        if (s == BB * TT) { ids = (const int*)d_in[i]; }
        else if (s == 50000 * DD) { emb = (const float*)d_in[i]; }
        else if (s == DD * DD * KK) { cw = (const float*)d_in[i]; }
        else if (s == DD) { cb = (const float*)d_in[i]; }
        else if (s == LL * DD) { U = (const float*)d_in[i]; }
        else if (s == LL) { fb = (const float*)d_in[i]; }
    }
    float* out = (float*)d_out;

    k_wsplit<<<(KK * DD * DD + 255) / 256, 256>>>(cw);
    k_usplit<<<(LL * DD + 255) / 256, 256>>>(U);
    k_gather<<<(BB * TT * DD + 255) / 256, 256>>>(ids, emb);
    k_conv<<<dim3(TPAD / 128, OP2 / 128, BB), 256>>>(cb);
    k_attn<<<dim3(LP / 128, BB), 256>>>(fb, out);
}

// round 10
// speedup vs baseline: 2.3605x; 1.0476x over previous
#include <cuda_runtime.h>
#include <cuda_bf16.h>
#include <cstdint>
#include <math.h>

typedef unsigned int u32;

// Problem dims
#define BB   8
#define TT   2048
#define DD   300
#define KK   10
#define LL   8921
#define TP   2057     // TT + KK - 1
#define LP   8960     // L padded to 70*128
#define OP2  384      // o padded to 3*128
#define DP   320      // d padded to 20*16
#define TPAD 2176     // t' padded to 17*128
#define ETR  2208     // embed rows: 9 halo + 2048 + tail zeros
#define SSTR 40       // smem row stride in bf16 (80B)

// Dynamic smem stage layout (bytes)
#define OFF_AL    10240
#define OFF_BH    20480
#define OFF_BL    30720
#define STG_BYTES 40960

// Scratch (device globals, zero-initialized; padding regions never written)
__device__ __align__(16) __nv_bfloat16 g_Ehi[BB * ETR * DP];   // [b][9+tau][d]
__device__ __align__(16) __nv_bfloat16 g_Elo[BB * ETR * DP];
__device__ __align__(16) __nv_bfloat16 g_Whi[KK * OP2 * DP];   // [k][o][i]
__device__ __align__(16) __nv_bfloat16 g_Wlo[KK * OP2 * DP];
__device__ __align__(16) __nv_bfloat16 g_Uhi[LP * DP];         // [l][d]
__device__ __align__(16) __nv_bfloat16 g_Ulo[LP * DP];
__device__ __align__(16) __nv_bfloat16 g_Hthi[BB * TPAD * DP]; // [b][t][o]
__device__ __align__(16) __nv_bfloat16 g_Htlo[BB * TPAD * DP];

// ---------------------------------------------------------------------------
// PTX helpers
// ---------------------------------------------------------------------------
__device__ __forceinline__ u32 smem_u32(const void* p) {
    return (u32)__cvta_generic_to_shared(p);
}

__device__ __forceinline__ void ldsm4(u32* r, u32 addr) {
    asm volatile("ldmatrix.sync.aligned.m8n8.x4.shared.b16 {%0,%1,%2,%3}, [%4];"
                 : "=r"(r[0]), "=r"(r[1]), "=r"(r[2]), "=r"(r[3])
                 : "r"(addr));
}

__device__ __forceinline__ void mma16816(float* d, const u32* a, const u32* b) {
    asm volatile(
        "mma.sync.aligned.m16n8k16.row.col.f32.bf16.bf16.f32 "
        "{%0,%1,%2,%3}, {%4,%5,%6,%7}, {%8,%9}, {%0,%1,%2,%3};"
        : "+f"(d[0]), "+f"(d[1]), "+f"(d[2]), "+f"(d[3])
        : "r"(a[0]), "r"(a[1]), "r"(a[2]), "r"(a[3]), "r"(b[0]), "r"(b[1]));
}

__device__ __forceinline__ void cpa16(u32 dst, const void* src) {
    asm volatile("cp.async.cg.shared.global [%0], [%1], 16;" :: "r"(dst), "l"(src));
}

__device__ __forceinline__ void cpa_commit() {
    asm volatile("cp.async.commit_group;");
}

__device__ __forceinline__ void cpa_wait1() {
    asm volatile("cp.async.wait_group 1;");
}

__device__ __forceinline__ void cpa_wait0() {
    asm volatile("cp.async.wait_group 0;");
}

// ---------------------------------------------------------------------------
// Kernel 1: embedding gather + bf16 hi/lo split -> Ehi/Elo[b][9+tau][d]
// ---------------------------------------------------------------------------
__global__ void k_gather(const int* __restrict__ ids, const float* __restrict__ emb) {
    int idx = blockIdx.x * 256 + threadIdx.x;
    if (idx >= BB * TT * DD) { return; }
    int d = idx % DD;
    int tok = idx / DD;
    int b = tok / TT;
    int tau = tok - b * TT;
    int row = ids[tok];
    float v = emb[row * DD + d];
    __nv_bfloat16 h = __float2bfloat16(v);
    size_t o = ((size_t)b * ETR + 9 + tau) * DP + d;
    g_Ehi[o] = h;
    g_Elo[o] = __float2bfloat16(v - __bfloat162float(h));
}

// ---------------------------------------------------------------------------
// Kernel 2: conv_w (O,I,K) fp32 -> Whi/Wlo[k][o][i]
// ---------------------------------------------------------------------------
__global__ void k_wsplit(const float* __restrict__ w) {
    int idx = blockIdx.x * 256 + threadIdx.x;
    if (idx >= KK * DD * DD) { return; }
    int i = idx % DD;
    int rem = idx / DD;
    int o = rem % DD;
    int k = rem / DD;
    float v = w[(o * DD + i) * KK + k];
    __nv_bfloat16 h = __float2bfloat16(v);
    size_t dst = ((size_t)k * OP2 + o) * DP + i;
    g_Whi[dst] = h;
    g_Wlo[dst] = __float2bfloat16(v - __bfloat162float(h));
}

// ---------------------------------------------------------------------------
// Kernel 3: U fp32 [l][d] -> bf16 hi/lo split [l][DP]
// ---------------------------------------------------------------------------
__global__ void k_usplit(const float* __restrict__ U) {
    int idx = blockIdx.x * 256 + threadIdx.x;
    if (idx >= LL * DD) { return; }
    int l = idx / DD;
    int d = idx - l * DD;
    float u = U[idx];
    __nv_bfloat16 h = __float2bfloat16(u);
    g_Uhi[l * DP + d] = h;
    g_Ulo[l * DP + d] = __float2bfloat16(u - __bfloat162float(h));
}

// ---------------------------------------------------------------------------
// cp.async stage issue for conv: phase p covers (k = p/10, d-chunk = p%10)
// ---------------------------------------------------------------------------
__device__ __forceinline__ void conv_issue(int p, int b, int o0, int t0,
                                           int tid, u32 smbase) {
    int k = p / 10;
    int ph = p - k * 10;
    int d0 = ph * 32;
    const __nv_bfloat16* Ah = g_Whi + ((size_t)k * OP2 + o0) * DP + d0;
    const __nv_bfloat16* Al = g_Wlo + ((size_t)k * OP2 + o0) * DP + d0;
    const __nv_bfloat16* Bh = g_Ehi + ((size_t)b * ETR + t0 + k) * DP + d0;
    const __nv_bfloat16* Bl = g_Elo + ((size_t)b * ETR + t0 + k) * DP + d0;
    u32 sb = smbase + (u32)((p & 1) * STG_BYTES);
#pragma unroll
    for (int it = 0; it < 2; it++) {
        int idx = tid + it * 256;
        int row = idx >> 2;
        int qd = (idx & 3) * 8;
        u32 so = sb + (u32)((row * SSTR + qd) * 2);
        size_t go = (size_t)row * DP + qd;
        cpa16(so,          Ah + go);
        cpa16(so + OFF_AL, Al + go);
        cpa16(so + OFF_BH, Bh + go);
        cpa16(so + OFF_BL, Bl + go);
    }
    cpa_commit();
}

// ---------------------------------------------------------------------------
// cp.async stage issue for attn: phase p covers (t-tile = p/10, d-chunk = p%10)
// ---------------------------------------------------------------------------
__device__ __forceinline__ void attn_issue(int p, int b, int l0,
                                           int tid, u32 smbase) {
    int tile = p / 10;
    int ph = p - tile * 10;
    int d0 = ph * 32;
    int t0 = tile * 128;
    const __nv_bfloat16* Ah = g_Uhi + (size_t)l0 * DP + d0;
    const __nv_bfloat16* Al = g_Ulo + (size_t)l0 * DP + d0;
    const __nv_bfloat16* Bh = g_Hthi + ((size_t)b * TPAD + t0) * DP + d0;
    const __nv_bfloat16* Bl = g_Htlo + ((size_t)b * TPAD + t0) * DP + d0;
    u32 sb = smbase + (u32)((p & 1) * STG_BYTES);
#pragma unroll
    for (int it = 0; it < 2; it++) {
        int idx = tid + it * 256;
        int row = idx >> 2;
        int qd = (idx & 3) * 8;
        u32 so = sb + (u32)((row * SSTR + qd) * 2);
        size_t go = (size_t)row * DP + qd;
        cpa16(so,          Ah + go);
        cpa16(so + OFF_AL, Al + go);
        cpa16(so + OFF_BH, Bh + go);
        cpa16(so + OFF_BL, Bl + go);
    }
    cpa_commit();
}

// ---------------------------------------------------------------------------
// Kernel 4: conv1d via pipelined bf16-split mma
//   C[o,t] = sum_k sum_i W[k][o][i] * E[t+k][i]; 100 pipelined phases
// ---------------------------------------------------------------------------
__global__ void __launch_bounds__(256, 2) k_conv(const float* __restrict__ conv_b) {
    extern __shared__ __align__(16) char dynsm[];
    int t0 = blockIdx.x * 128;
    int o0 = blockIdx.y * 128;
    int b  = blockIdx.z;
    int tid = threadIdx.x;
    int lane = tid & 31;
    int warp = tid >> 5;
    int warp_m = warp >> 1;
    int warp_n = warp & 1;
    int g = lane >> 2;
    int q = lane & 3;

    u32 smbase = smem_u32(dynsm);

    u32 aoff0 = (u32)(((warp_m * 32 + 0  + (lane & 15)) * SSTR + (lane >> 4) * 8) * 2);
    u32 aoff1 = (u32)(((warp_m * 32 + 16 + (lane & 15)) * SSTR + (lane >> 4) * 8) * 2);
    u32 boff[4];
    {
        int bidx = lane >> 3;
        int brow_add = (bidx >> 1) * 8 + (lane & 7);
        int bcol = (bidx & 1) * 8;
#pragma unroll
        for (int j2 = 0; j2 < 4; j2++) {
            boff[j2] = (u32)(((warp_n * 64 + j2 * 16 + brow_add) * SSTR + bcol) * 2);
        }
    }

    float acc[2][8][4];
#pragma unroll
    for (int mt = 0; mt < 2; mt++) {
#pragma unroll
        for (int j = 0; j < 8; j++) {
#pragma unroll
            for (int c = 0; c < 4; c++) { acc[mt][j][c] = 0.f; }
        }
    }

    const int NPH = 100;
    conv_issue(0, b, o0, t0, tid, smbase);

    for (int p = 0; p < NPH; p++) {
        if (p + 1 < NPH) {
            conv_issue(p + 1, b, o0, t0, tid, smbase);
            cpa_wait1();
        } else {
            cpa_wait0();
        }
        __syncthreads();

        u32 sb = smbase + (u32)((p & 1) * STG_BYTES);
#pragma unroll
        for (int kc = 0; kc < 2; kc++) {
            u32 kb = (u32)(kc * 32);
            u32 ah0[4];
            u32 ah1[4];
            u32 al0[4];
            u32 al1[4];
            u32 bhf[4][4];
            u32 blf[4][4];

            ldsm4(ah0, sb + aoff0 + kb);
            ldsm4(ah1, sb + aoff1 + kb);
#pragma unroll
            for (int j2 = 0; j2 < 4; j2++) { ldsm4(bhf[j2], sb + OFF_BH + boff[j2] + kb); }

#pragma unroll
            for (int j = 0; j < 8; j++) {
                const u32* bp = &bhf[j >> 1][(j & 1) * 2];
                mma16816(acc[0][j], ah0, bp);
                mma16816(acc[1][j], ah1, bp);
            }

            ldsm4(al0, sb + OFF_AL + aoff0 + kb);
            ldsm4(al1, sb + OFF_AL + aoff1 + kb);
#pragma unroll
            for (int j = 0; j < 8; j++) {
                const u32* bp = &bhf[j >> 1][(j & 1) * 2];
                mma16816(acc[0][j], al0, bp);
                mma16816(acc[1][j], al1, bp);
            }

#pragma unroll
            for (int j2 = 0; j2 < 4; j2++) { ldsm4(blf[j2], sb + OFF_BL + boff[j2] + kb); }
#pragma unroll
            for (int j = 0; j < 8; j++) {
                const u32* bp = &blf[j >> 1][(j & 1) * 2];
                mma16816(acc[0][j], ah0, bp);
                mma16816(acc[1][j], ah1, bp);
            }
        }
        __syncthreads();
    }

    // Epilogue: bias + relu, hi/lo split, transposed element stores to [t][o]
#pragma unroll
    for (int mt = 0; mt < 2; mt++) {
#pragma unroll
        for (int ch = 0; ch < 2; ch++) {
            int o = o0 + warp_m * 32 + mt * 16 + g + ch * 8;
            if (o < DD) {
                float bias = conv_b[o];
#pragma unroll
                for (int j = 0; j < 8; j++) {
#pragma unroll
                    for (int bb2 = 0; bb2 < 2; bb2++) {
                        int t = t0 + warp_n * 64 + j * 8 + q * 2 + bb2;
                        if (t < TP) {
                            float v = fmaxf(acc[mt][j][ch * 2 + bb2] + bias, 0.f);
                            __nv_bfloat16 h = __float2bfloat16(v);
                            size_t dst = ((size_t)b * TPAD + t) * DP + o;
                            g_Hthi[dst] = h;
                            g_Htlo[dst] = __float2bfloat16(v - __bfloat162float(h));
                        }
                    }
                }
            }
        }
    }
}

// ---------------------------------------------------------------------------
// Kernel 5: fused score-GEMM (pipelined bf16-split mma) + online softmax
//   170 pipelined phases over 17 t-tiles x 10 d-chunks
// ---------------------------------------------------------------------------
__global__ void __launch_bounds__(256, 2) k_attn(const float* __restrict__ fc_bias,
                                                 float* __restrict__ out) {
    extern __shared__ __align__(16) char dynsm[];
    __shared__ float s_m[128];
    __shared__ float s_e[128];
    __shared__ float s_s[128];
    __shared__ float p_m[2][128];
    __shared__ float p_e[2][128];
    __shared__ float p_s[2][128];

    int l0 = blockIdx.x * 128;
    int b  = blockIdx.y;
    int tid = threadIdx.x;
    int lane = tid & 31;
    int warp = tid >> 5;
    int warp_m = warp >> 1;
    int warp_n = warp & 1;
    int g = lane >> 2;
    int q = lane & 3;

    if (tid < 128) {
        s_m[tid] = -INFINITY;
        s_e[tid] = 0.f;
        s_s[tid] = 0.f;
    }

    u32 smbase = smem_u32(dynsm);

    u32 aoff0 = (u32)(((warp_m * 32 + 0  + (lane & 15)) * SSTR + (lane >> 4) * 8) * 2);
    u32 aoff1 = (u32)(((warp_m * 32 + 16 + (lane & 15)) * SSTR + (lane >> 4) * 8) * 2);
    u32 boff[4];
    {
        int bidx = lane >> 3;
        int brow_add = (bidx >> 1) * 8 + (lane & 7);
        int bcol = (bidx & 1) * 8;
#pragma unroll
        for (int j2 = 0; j2 < 4; j2++) {
            boff[j2] = (u32)(((warp_n * 64 + j2 * 16 + brow_add) * SSTR + bcol) * 2);
        }
    }

    const int NPH = 170;
    attn_issue(0, b, l0, tid, smbase);

    float acc[2][8][4];

    for (int p = 0; p < NPH; p++) {
        int tile = p / 10;
        int ph = p - tile * 10;

        if (ph == 0) {
#pragma unroll
            for (int mt = 0; mt < 2; mt++) {
#pragma unroll
                for (int j = 0; j < 8; j++) {
#pragma unroll
                    for (int c = 0; c < 4; c++) { acc[mt][j][c] = 0.f; }
                }
            }
        }

        if (p + 1 < NPH) {
            attn_issue(p + 1, b, l0, tid, smbase);
            cpa_wait1();
        } else {
            cpa_wait0();
        }
        __syncthreads();

        u32 sb = smbase + (u32)((p & 1) * STG_BYTES);
#pragma unroll
        for (int kc = 0; kc < 2; kc++) {
            u32 kb = (u32)(kc * 32);
            u32 ah0[4];
            u32 ah1[4];
            u32 al0[4];
            u32 al1[4];
            u32 bhf[4][4];
            u32 blf[4][4];

            ldsm4(ah0, sb + aoff0 + kb);
            ldsm4(ah1, sb + aoff1 + kb);
#pragma unroll
            for (int j2 = 0; j2 < 4; j2++) { ldsm4(bhf[j2], sb + OFF_BH + boff[j2] + kb); }

#pragma unroll
            for (int j = 0; j < 8; j++) {
                const u32* bp = &bhf[j >> 1][(j & 1) * 2];
                mma16816(acc[0][j], ah0, bp);
                mma16816(acc[1][j], ah1, bp);
            }

            ldsm4(al0, sb + OFF_AL + aoff0 + kb);
            ldsm4(al1, sb + OFF_AL + aoff1 + kb);
#pragma unroll
            for (int j = 0; j < 8; j++) {
                const u32* bp = &bhf[j >> 1][(j & 1) * 2];
                mma16816(acc[0][j], al0, bp);
                mma16816(acc[1][j], al1, bp);
            }

#pragma unroll
            for (int j2 = 0; j2 < 4; j2++) { ldsm4(blf[j2], sb + OFF_BL + boff[j2] + kb); }
#pragma unroll
            for (int j = 0; j < 8; j++) {
                const u32* bp = &blf[j >> 1][(j & 1) * 2];
                mma16816(acc[0][j], ah0, bp);
                mma16816(acc[1][j], ah1, bp);
            }
        }

        if (ph == 9) {
            // per-warp partial softmax stats for this t-tile
            int t0 = tile * 128;
#pragma unroll
            for (int mt = 0; mt < 2; mt++) {
#pragma unroll
                for (int ch = 0; ch < 2; ch++) {
                    int row = warp_m * 32 + mt * 16 + g + ch * 8;
                    float mx = -INFINITY;
#pragma unroll
                    for (int j = 0; j < 8; j++) {
#pragma unroll
                        for (int bb2 = 0; bb2 < 2; bb2++) {
                            int t = t0 + warp_n * 64 + j * 8 + q * 2 + bb2;
                            if (t < TP) { mx = fmaxf(mx, acc[mt][j][ch * 2 + bb2]); }
                        }
                    }
                    mx = fmaxf(mx, __shfl_xor_sync(0xffffffffu, mx, 1));
                    mx = fmaxf(mx, __shfl_xor_sync(0xffffffffu, mx, 2));

                    float pe = 0.f;
                    float ps = 0.f;
#pragma unroll
                    for (int j = 0; j < 8; j++) {
#pragma unroll
                        for (int bb2 = 0; bb2 < 2; bb2++) {
                            int t = t0 + warp_n * 64 + j * 8 + q * 2 + bb2;
                            if (t < TP) {
                                float v = acc[mt][j][ch * 2 + bb2];
                                float pv = __expf(v - mx);
                                pe += pv;
                                ps += pv * v;
                            }
                        }
                    }
                    pe += __shfl_xor_sync(0xffffffffu, pe, 1);
                    ps += __shfl_xor_sync(0xffffffffu, ps, 1);
                    pe += __shfl_xor_sync(0xffffffffu, pe, 2);
                    ps += __shfl_xor_sync(0xffffffffu, ps, 2);

                    if (q == 0) {
                        p_m[warp_n][row] = mx;
                        p_e[warp_n][row] = pe;
                        p_s[warp_n][row] = ps;
                    }
                }
            }
            __syncthreads();

            if (tid < 128) {
                float mo = s_m[tid];
                float eo = s_e[tid];
                float so = s_s[tid];
#pragma unroll
                for (int pp = 0; pp < 2; pp++) {
                    float mx = p_m[pp][tid];
                    float pe = p_e[pp][tid];
                    float ps = p_s[pp][tid];
                    float mn = fmaxf(mo, mx);
                    float e1 = __expf(mo - mn);
                    float e2 = __expf(mx - mn);
                    eo = eo * e1 + pe * e2;
                    so = so * e1 + ps * e2;
                    mo = mn;
                }
                s_m[tid] = mo;
                s_e[tid] = eo;
                s_s[tid] = so;
            }
        }
        __syncthreads();
    }

    if (tid < 128) {
        int l = l0 + tid;
        if (l < LL) { out[b * LL + l] = s_s[tid] / s_e[tid] + fc_bias[l]; }
    }
}

// ---------------------------------------------------------------------------
// Launch
// ---------------------------------------------------------------------------
extern "C" void kernel_launch(void* const* d_in, const int* in_sizes, int n_in,
                              void* d_out, int out_size) {
    const int* ids = nullptr;
    const float* emb = nullptr;
    const float* cw = nullptr;
    const float* cb = nullptr;
    const float* U = nullptr;
    const float* fb = nullptr;
    for (int i = 0; i < n_in; i++) {
        int s = in_sizes[i];
        if (s == BB * TT) { ids = (const int*)d_in[i]; }
        else if (s == 50000 * DD) { emb = (const float*)d_in[i]; }
        else if (s == DD * DD * KK) { cw = (const float*)d_in[i]; }
        else if (s == DD) { cb = (const float*)d_in[i]; }
        else if (s == LL * DD) { U = (const float*)d_in[i]; }
        else if (s == LL) { fb = (const float*)d_in[i]; }
    }
    float* out = (float*)d_out;

    const int DYN = 2 * STG_BYTES;  // 81920 bytes
    cudaFuncSetAttribute(k_conv, cudaFuncAttributeMaxDynamicSharedMemorySize, DYN);
    cudaFuncSetAttribute(k_attn, cudaFuncAttributeMaxDynamicSharedMemorySize, DYN);

    k_wsplit<<<(KK * DD * DD + 255) / 256, 256>>>(cw);
    k_usplit<<<(LL * DD + 255) / 256, 256>>>(U);
    k_gather<<<(BB * TT * DD + 255) / 256, 256>>>(ids, emb);
    k_conv<<<dim3(TPAD / 128, OP2 / 128, BB), 256, DYN>>>(cb);
    k_attn<<<dim3(LP / 128, BB), 256, DYN>>>(fb, out);
}